// round 1
// baseline (speedup 1.0000x reference)
#include <cuda_runtime.h>
#include <cuda_bf16.h>
#include <cstdint>

// ---------------------------------------------------------------------------
// QTT-3D sampling via full prefix/suffix table precomputation.
//
// ranks: [1,8,64,256,256,256,256? -> actually [1,8,64,256,256,256,64,8,1]
// core0 (1,8,8) core1 (8,8,64) core2 (64,8,256) core3 (256,8,256)
// core4 (256,8,256) core5 (256,8,64) core6 (64,8,8) core7 (8,8,1)
//
// prefix P = g0*512+g1*64+g2*8+g3  -> M0123[P][256]
// suffix S = g4*512+g5*64+g6*8+g7  -> W4567[S][256]
// out[n] = dot(M0123[P(n)], W4567[S(n)])
// ---------------------------------------------------------------------------

__device__ __align__(128) float g_M01[64 * 64];
__device__ __align__(128) float g_W67[64 * 64];
__device__ __align__(128) float g_M012[512 * 256];
__device__ __align__(128) float g_W567[512 * 256];
__device__ __align__(128) float g_M0123[4096 * 256];
__device__ __align__(128) float g_W4567[4096 * 256];

// ---------------- Kernel A: M01 (64x64) and W67 (64x64) -------------------
// grid 128 blocks x 64 threads
__global__ void __launch_bounds__(64) qtt_precompA(
    const float* __restrict__ c0, const float* __restrict__ c1,
    const float* __restrict__ c6, const float* __restrict__ c7)
{
    int b = blockIdx.x;
    int t = threadIdx.x;  // 0..63
    if (b < 64) {
        int g0 = b >> 3, g1 = b & 7;
        float acc = 0.f;
#pragma unroll
        for (int r = 0; r < 8; r++)
            acc += c0[g0 * 8 + r] * c1[(r * 8 + g1) * 64 + t];
        g_M01[b * 64 + t] = acc;
    } else {
        int q = b - 64;
        int g6 = q >> 3, g7 = q & 7;
        float acc = 0.f;
#pragma unroll
        for (int j = 0; j < 8; j++)
            acc += c6[(t * 8 + g6) * 8 + j] * c7[j * 8 + g7];
        g_W67[q * 64 + t] = acc;
    }
}

// ---------------- Kernel B: M012 (512x256) and W567 (512x256) -------------
// grid 1024 blocks x 256 threads
__global__ void __launch_bounds__(256) qtt_precompB(
    const float* __restrict__ c2, const float* __restrict__ c5)
{
    __shared__ float sv[64];
    int b = blockIdx.x;
    int t = threadIdx.x;  // 0..255
    if (b < 512) {
        int p01 = b >> 3, g2 = b & 7;
        if (t < 64) sv[t] = g_M01[p01 * 64 + t];
        __syncthreads();
        float acc = 0.f;
#pragma unroll 16
        for (int r = 0; r < 64; r++)
            acc += sv[r] * c2[(r * 8 + g2) * 256 + t];
        g_M012[b * 256 + t] = acc;
    } else {
        int c = b - 512;
        int g5 = c >> 6, q = c & 63;
        if (t < 64) sv[t] = g_W67[q * 64 + t];
        __syncthreads();
        const float4* row = (const float4*)(c5 + (t * 8 + g5) * 64);
        float acc = 0.f;
#pragma unroll
        for (int u = 0; u < 16; u++) {
            float4 rv = row[u];
            acc += rv.x * sv[u * 4 + 0] + rv.y * sv[u * 4 + 1] +
                   rv.z * sv[u * 4 + 2] + rv.w * sv[u * 4 + 3];
        }
        g_W567[c * 256 + t] = acc;
    }
}

// ---------------- Kernel C: 16 dense GEMMs 512x256x256 --------------------
// z in [0,8): M0123 rows m*8+g3  = M012(512x256) @ core3[:,g3,:](256x256)
// z in [8,16): W4567 rows g4*512+m = W567(512x256) @ core4[:,g4,:]^T
// Block tile 128x128, BK=16, 256 threads, 8x8 microtile.
#define QBM 128
#define QBN 128
#define QBK 16

__global__ void __launch_bounds__(256) qtt_gemm(
    const float* __restrict__ core3, const float* __restrict__ core4)
{
    const int z = blockIdx.z;
    const bool prefix = (z < 8);
    const int g = prefix ? z : (z - 8);
    const float* __restrict__ A = prefix ? g_M012 : g_W567;
    const float* __restrict__ core = prefix ? core3 : core4;

    const int m0 = blockIdx.x * QBM;   // 0..511 in steps of 128
    const int n0 = blockIdx.y * QBN;   // 0 or 128

    __shared__ __align__(16) float As[QBK * QBM];
    __shared__ __align__(16) float Bs[QBK * QBN];

    const int tid = threadIdx.x;
    const int tm = tid >> 4;        // 0..15
    const int tn = tid & 15;        // 0..15

    float c[8][8];
#pragma unroll
    for (int i = 0; i < 8; i++)
#pragma unroll
        for (int j = 0; j < 8; j++) c[i][j] = 0.f;

    for (int k0 = 0; k0 < 256; k0 += QBK) {
        __syncthreads();
        // ---- load A tile (128 rows x 16 k), store transposed As[k][m]
#pragma unroll
        for (int j = 0; j < 2; j++) {
            int i = tid + j * 256;          // 0..511
            int row = i >> 2;               // 0..127
            int kq = (i & 3) * 4;           // 0,4,8,12
            float4 v = *(const float4*)(A + (m0 + row) * 256 + k0 + kq);
            As[(kq + 0) * QBM + row] = v.x;
            As[(kq + 1) * QBM + row] = v.y;
            As[(kq + 2) * QBM + row] = v.z;
            As[(kq + 3) * QBM + row] = v.w;
        }
        // ---- load B tile Bs[k][n]
        if (prefix) {
            // B[k][n] = core3[((k0+k)*8+g)*256 + n0+n], contiguous in n
#pragma unroll
            for (int j = 0; j < 2; j++) {
                int i = tid + j * 256;      // 0..511
                int k = i >> 5;             // 0..15
                int n = (i & 31) * 4;       // 0..124
                float4 v = *(const float4*)(core + ((k0 + k) * 8 + g) * 256 + n0 + n);
                *(float4*)(Bs + k * QBN + n) = v;
            }
        } else {
            // B[k][n] = core4[((n0+n)*8+g)*256 + k0+k], contiguous in k
#pragma unroll
            for (int j = 0; j < 2; j++) {
                int i = tid + j * 256;
                int n = i >> 2;             // 0..127
                int kq = (i & 3) * 4;       // 0,4,8,12
                float4 v = *(const float4*)(core + ((n0 + n) * 8 + g) * 256 + k0 + kq);
                Bs[(kq + 0) * QBN + n] = v.x;
                Bs[(kq + 1) * QBN + n] = v.y;
                Bs[(kq + 2) * QBN + n] = v.z;
                Bs[(kq + 3) * QBN + n] = v.w;
            }
        }
        __syncthreads();
        // ---- compute
#pragma unroll
        for (int k = 0; k < QBK; k++) {
            float a[8], bb[8];
            *(float4*)(a)      = *(const float4*)(As + k * QBM + tm * 8);
            *(float4*)(a + 4)  = *(const float4*)(As + k * QBM + tm * 8 + 4);
            *(float4*)(bb)     = *(const float4*)(Bs + k * QBN + tn * 8);
            *(float4*)(bb + 4) = *(const float4*)(Bs + k * QBN + tn * 8 + 4);
#pragma unroll
            for (int i = 0; i < 8; i++)
#pragma unroll
                for (int j = 0; j < 8; j++)
                    c[i][j] = fmaf(a[i], bb[j], c[i][j]);
        }
    }

    // ---- store C
#pragma unroll
    for (int mi = 0; mi < 8; mi++) {
        int m = m0 + tm * 8 + mi;     // 0..511
        float* dst;
        if (prefix) dst = g_M0123 + (m * 8 + g) * 256 + n0 + tn * 8;
        else        dst = g_W4567 + (g * 512 + m) * 256 + n0 + tn * 8;
        *(float4*)(dst)     = make_float4(c[mi][0], c[mi][1], c[mi][2], c[mi][3]);
        *(float4*)(dst + 4) = make_float4(c[mi][4], c[mi][5], c[mi][6], c[mi][7]);
    }
}

// ---------------- Kernel D: sampling — one warp per sample ----------------
// out[n] = dot(M0123[P], W4567[S]); grid 512 x 256 threads (8 warps/block)
__global__ void __launch_bounds__(256) qtt_sample(
    const int* __restrict__ coords, float* __restrict__ out)
{
    int warp = (blockIdx.x * blockDim.x + threadIdx.x) >> 5;
    int lane = threadIdx.x & 31;
    if (warp >= 4096) return;

    int x = coords[warp * 3 + 0];
    int y = coords[warp * 3 + 1];
    int zc = coords[warp * 3 + 2];

    int P = 0, S = 0;
#pragma unroll
    for (int l = 0; l < 8; l++) {
        int sh = 7 - l;
        int b = (((x >> sh) & 1) << 2) | (((y >> sh) & 1) << 1) | ((zc >> sh) & 1);
        if (l < 4) P = (P << 3) | b;
        else       S = (S << 3) | b;
    }

    const float4* a = (const float4*)(g_M0123 + P * 256);
    const float4* w = (const float4*)(g_W4567 + S * 256);
    float4 a0 = a[lane], a1 = a[lane + 32];
    float4 b0 = w[lane], b1 = w[lane + 32];
    float acc = a0.x * b0.x + a0.y * b0.y + a0.z * b0.z + a0.w * b0.w
              + a1.x * b1.x + a1.y * b1.y + a1.z * b1.z + a1.w * b1.w;
#pragma unroll
    for (int o = 16; o > 0; o >>= 1)
        acc += __shfl_xor_sync(0xFFFFFFFFu, acc, o);
    if (lane == 0) out[warp] = acc;
}

// ---------------------------------------------------------------------------
extern "C" void kernel_launch(void* const* d_in, const int* in_sizes, int n_in,
                              void* d_out, int out_size)
{
    (void)in_sizes; (void)n_in; (void)out_size;
    const float* c0 = (const float*)d_in[0];
    const float* c1 = (const float*)d_in[1];
    const float* c2 = (const float*)d_in[2];
    const float* c3 = (const float*)d_in[3];
    const float* c4 = (const float*)d_in[4];
    const float* c5 = (const float*)d_in[5];
    const float* c6 = (const float*)d_in[6];
    const float* c7 = (const float*)d_in[7];
    const int* coords = (const int*)d_in[8];
    float* out = (float*)d_out;

    qtt_precompA<<<128, 64>>>(c0, c1, c6, c7);
    qtt_precompB<<<1024, 256>>>(c2, c5);
    dim3 grid(4, 2, 16);
    qtt_gemm<<<grid, 256>>>(c3, c4);
    qtt_sample<<<512, 256>>>(coords, out);
}